// round 11
// baseline (speedup 1.0000x reference)
#include <cuda_runtime.h>
#include <math.h>

#define BB 64
#define DD 512
#define HH 8
#define EPSF 1e-8f
#define NTHR 128          // 8 heads x 16 i-values per CTA
#define ITILE 16
#define NTILES (DD / ITILE)   // 32

typedef unsigned long long ull;

__device__ __forceinline__ ull pk2(float lo, float hi) {
    ull r; asm("mov.b64 %0, {%1, %2};" : "=l"(r) : "f"(lo), "f"(hi)); return r;
}
__device__ __forceinline__ void upk2(ull v, float& lo, float& hi) {
    asm("mov.b64 {%0, %1}, %2;" : "=f"(lo), "=f"(hi) : "l"(v));
}
__device__ __forceinline__ ull fma2(ull a, ull b, ull c) {
    ull r; asm("fma.rn.f32x2 %0, %1, %2, %3;" : "=l"(r) : "l"(a), "l"(b), "l"(c)); return r;
}
__device__ __forceinline__ ull add2(ull a, ull b) {
    ull r; asm("add.rn.f32x2 %0, %1, %2;" : "=l"(r) : "l"(a), "l"(b)); return r;
}

#define MAGICF 12582912.0f   // 1.5 * 2^23

__global__ __launch_bounds__(NTHR)
void flattn_kernel(const float* __restrict__ x,
                   const float* __restrict__ alphas,
                   const float* __restrict__ betas,
                   float* __restrict__ out)
{
    __shared__ __align__(16) float xs[DD];
    __shared__ float partial[NTHR];   // [h][i_loc]

    const int b    = blockIdx.y;
    const int tile = blockIdx.x;      // 0..31, block of 16 i-rows
    const int tid  = threadIdx.x;
    const int h     = tid >> 4;       // 0..7
    const int i_loc = tid & 15;       // 0..15
    const int i     = tile * ITILE + i_loc;

    // Stage x row in shared (vectorized).
    const float4* xrow4 = (const float4*)(x + b * DD);
    float4* xs4w = (float4*)xs;
    #pragma unroll
    for (int k = tid; k < DD / 4; k += NTHR) xs4w[k] = xrow4[k];
    __syncthreads();

    const float aq = alphas[h * 3 + 0];
    const float ak = alphas[h * 3 + 1];
    const float av = alphas[h * 3 + 2];
    const float bq = betas[h * 3 + 0];
    const float bk = betas[h * 3 + 1];

    const float inv_sqrt_d = 0.044194173824159216f;  // 1/sqrt(512)
    const float INV_L2E    = 0.6931471805599453f;    // ln(2)

    // L2E-scaled domain: rcp(max(|d'|, eps')) = L2E * s  (feeds exp2 directly).
    const float xi  = xs[i];
    const float c   = bq - fmaf(ak, xi, bk);   // q_j - k_i = aq*x_j + c
    const float aqs = aq * INV_L2E;
    const float cs  = c  * INV_L2E;
    const float EPS_S = EPSF * INV_L2E;

    const ull aq2 = pk2(aqs, aqs);
    const ull c2  = pk2(cs, cs);

    const ulonglong2* xs2 = (const ulonglong2*)xs;

    // ---- Pass 1: tmin' = min_j |aqs*x_j + cs|  (packed FFMA2 + FMNMX|.|) ----
    float t0 = 3.0e38f, t1 = 3.0e38f, t2m = 3.0e38f, t3 = 3.0e38f;
    #pragma unroll 8
    for (int jq = 0; jq < DD / 4; jq++) {
        ulonglong2 xq = xs2[jq];
        ull d01 = fma2(aq2, xq.x, c2);
        ull d23 = fma2(aq2, xq.y, c2);
        float da, db, dc, dd;
        upk2(d01, da, db);
        upk2(d23, dc, dd);
        t0  = fminf(t0,  fabsf(da));
        t1  = fminf(t1,  fabsf(db));
        t2m = fminf(t2m, fabsf(dc));
        t3  = fminf(t3,  fabsf(dd));
    }
    float tmin = fmaxf(fminf(fminf(t0, t1), fminf(t2m, t3)), EPS_S);
    float mL2E;   // = L2E * max_j s_j  (rcp monotone decreasing)
    asm("rcp.approx.f32 %0, %1;" : "=f"(mL2E) : "f"(tmin));
    const float negm   = -mL2E;
    // Guard band 64 (NOT 120): ulp(mL2E) can be 16, so i stays >= ~-80 and the
    // exponent insert bits(p) + i<<23 can never wrap through the sign bit.
    const float clampv = mL2E - 64.0f;

    // exp2 poly coeffs (2^f, f in [-0.5, 0.5]), packed
    const ull C1 = pk2(6.9314720284e-1f, 6.9314720284e-1f);
    const ull C2 = pk2(2.4022647913e-1f, 2.4022647913e-1f);
    const ull C3 = pk2(5.5503324712e-2f, 5.5503324712e-2f);
    const ull C4 = pk2(9.6184373577e-3f, 9.6184373577e-3f);
    const ull ONE2   = pk2(1.0f, 1.0f);
    const ull NEG1   = pk2(-1.0f, -1.0f);
    const ull MAG2   = pk2(MAGICF, MAGICF);
    const ull NMAG2  = pk2(-MAGICF, -MAGICF);
    const ull NEGM2  = pk2(negm, negm);

    // ---- Pass 2: e = 2^(r - mL2E) via fma-pipe exp2; accumulate f32x2 ----
    ull w2 = 0ULL, w2b = 0ULL, wx2 = 0ULL, wx2b = 0ULL;
    #pragma unroll 4
    for (int jq = 0; jq < DD / 4; jq++) {
        ulonglong2 xq = xs2[jq];
        ull x01 = xq.x, x23 = xq.y;

        ull d01 = fma2(aq2, x01, c2);
        ull d23 = fma2(aq2, x23, c2);
        float da, db, dc, dd;
        upk2(d01, da, db);
        upk2(d23, dc, dd);

        float ta = fmaxf(fabsf(da), EPS_S);
        float tb = fmaxf(fabsf(db), EPS_S);
        float tc = fmaxf(fabsf(dc), EPS_S);
        float td = fmaxf(fabsf(dd), EPS_S);

        float ra, rb, rc, rd;
        asm("rcp.approx.f32 %0, %1;" : "=f"(ra) : "f"(ta));
        asm("rcp.approx.f32 %0, %1;" : "=f"(rb) : "f"(tb));
        asm("rcp.approx.f32 %0, %1;" : "=f"(rc) : "f"(tc));
        asm("rcp.approx.f32 %0, %1;" : "=f"(rd) : "f"(td));

        // clamp (scalar FMNMX) then pack; a = r - mL2E in [~-80, 0]
        ull r01 = pk2(fmaxf(ra, clampv), fmaxf(rb, clampv));
        ull r23 = pk2(fmaxf(rc, clampv), fmaxf(rd, clampv));
        ull a01 = add2(r01, NEGM2);
        ull a23 = add2(r23, NEGM2);

        // i = round(a) via magic; f = a - i
        ull t01 = add2(a01, MAG2);
        ull t23 = add2(a23, MAG2);
        ull u01 = add2(t01, NMAG2);
        ull u23 = add2(t23, NMAG2);
        ull f01 = fma2(u01, NEG1, a01);
        ull f23 = fma2(u23, NEG1, a23);

        // p = 2^f (degree-4)
        ull p01 = fma2(C4, f01, C3);
        ull p23 = fma2(C4, f23, C3);
        p01 = fma2(p01, f01, C2);
        p23 = fma2(p23, f23, C2);
        p01 = fma2(p01, f01, C1);
        p23 = fma2(p23, f23, C1);
        p01 = fma2(p01, f01, ONE2);
        p23 = fma2(p23, f23, ONE2);

        // exponent insert: bits(e) = bits(p) + bits(t)*2^23  (per 32-bit lane;
        // magic-constant bias bits shift out mod 2^32)
        unsigned e0 = (unsigned)p01 + (unsigned)t01 * 0x800000u;
        unsigned e1 = (unsigned)(p01 >> 32) + (unsigned)(t01 >> 32) * 0x800000u;
        unsigned e2 = (unsigned)p23 + (unsigned)t23 * 0x800000u;
        unsigned e3 = (unsigned)(p23 >> 32) + (unsigned)(t23 >> 32) * 0x800000u;
        ull e01 = (ull)e0 | ((ull)e1 << 32);
        ull e23 = (ull)e2 | ((ull)e3 << 32);

        w2   = add2(w2,  e01);
        w2b  = add2(w2b, e23);
        wx2  = fma2(e01, x01, wx2);
        wx2b = fma2(e23, x23, wx2b);
    }
    float wl, wh, wbl, wbh, wxl, wxh, wxbl, wxbh;
    upk2(w2, wl, wh);
    upk2(w2b, wbl, wbh);
    upk2(wx2, wxl, wxh);
    upk2(wx2b, wxbl, wxbh);
    float wsum = (wl + wh) + (wbl + wbh);
    float wx   = (wxl + wxh) + (wxbl + wxbh);

    float rw;
    asm("rcp.approx.f32 %0, %1;" : "=f"(rw) : "f"(wsum));
    partial[tid] = av * inv_sqrt_d * (wx * rw);
    __syncthreads();

    // ---- Cross-head sum (8 values per output), single coalesced store ----
    if (tid < ITILE) {
        float bconst = 0.0f;
        #pragma unroll
        for (int hh = 0; hh < HH; hh++) bconst += betas[hh * 3 + 2];

        float s = 0.0f;
        #pragma unroll
        for (int hh = 0; hh < HH; hh++) s += partial[hh * ITILE + tid];

        out[b * DD + tile * ITILE + tid] =
            xs[tile * ITILE + tid] + s + bconst * inv_sqrt_d;
    }
}

extern "C" void kernel_launch(void* const* d_in, const int* in_sizes, int n_in,
                              void* d_out, int out_size)
{
    const float* x      = (const float*)d_in[0];
    const float* alphas = (const float*)d_in[1];
    const float* betas  = (const float*)d_in[2];
    float* out = (float*)d_out;

    dim3 grid(NTILES, BB);   // (32, 64) = 2048 CTAs
    dim3 block(NTHR);
    flattn_kernel<<<grid, block>>>(x, alphas, betas, out);
}

// round 12
// speedup vs baseline: 1.1533x; 1.1533x over previous
#include <cuda_runtime.h>
#include <math.h>

#define BB 64
#define DD 512
#define HH 8
#define EPSF 1e-8f
#define NTHR 128          // 8 heads x 16 i-values per CTA
#define ITILE 16
#define NTILES (DD / ITILE)   // 32

typedef unsigned long long ull;

__device__ __forceinline__ ull pk2(float lo, float hi) {
    ull r; asm("mov.b64 %0, {%1, %2};" : "=l"(r) : "f"(lo), "f"(hi)); return r;
}
__device__ __forceinline__ void upk2(ull v, float& lo, float& hi) {
    asm("mov.b64 {%0, %1}, %2;" : "=f"(lo), "=f"(hi) : "l"(v));
}
__device__ __forceinline__ ull fma2(ull a, ull b, ull c) {
    ull r; asm("fma.rn.f32x2 %0, %1, %2, %3;" : "=l"(r) : "l"(a), "l"(b), "l"(c)); return r;
}
__device__ __forceinline__ ull add2(ull a, ull b) {
    ull r; asm("add.rn.f32x2 %0, %1, %2;" : "=l"(r) : "l"(a), "l"(b)); return r;
}

__global__ __launch_bounds__(NTHR)
void flattn_kernel(const float* __restrict__ x,
                   const float* __restrict__ alphas,
                   const float* __restrict__ betas,
                   float* __restrict__ out)
{
    __shared__ __align__(16) float xs[DD];
    __shared__ float partial[NTHR];   // [h][i_loc]

    const int b    = blockIdx.y;
    const int tile = blockIdx.x;      // 0..31, block of 16 i-rows
    const int tid  = threadIdx.x;
    const int h     = tid >> 4;       // 0..7
    const int i_loc = tid & 15;       // 0..15
    const int i     = tile * ITILE + i_loc;

    // Stage x row in shared (vectorized).
    const float4* xrow4 = (const float4*)(x + b * DD);
    float4* xs4w = (float4*)xs;
    #pragma unroll
    for (int k = tid; k < DD / 4; k += NTHR) xs4w[k] = xrow4[k];
    __syncthreads();

    const float aq = alphas[h * 3 + 0];
    const float ak = alphas[h * 3 + 1];
    const float av = alphas[h * 3 + 2];
    const float bq = betas[h * 3 + 0];
    const float bk = betas[h * 3 + 1];

    const float inv_sqrt_d = 0.044194173824159216f;  // 1/sqrt(512)
    const float INV_L2E    = 0.6931471805599453f;    // ln(2)

    // L2E-scaled domain: rcp(max(|d'|, eps')) = L2E * s feeds ex2 directly.
    const float xi  = xs[i];
    const float c   = bq - fmaf(ak, xi, bk);   // q_j - k_i = aq*x_j + c
    const float aqs = aq * INV_L2E;
    const float cs  = c  * INV_L2E;
    const float EPS_S = EPSF * INV_L2E;

    const ull aq2 = pk2(aqs, aqs);
    const ull c2  = pk2(cs, cs);

    const ulonglong2* xs2 = (const ulonglong2*)xs;

    // ---- Pass 1: tmin' = min_j max(|aqs*x_j + cs|, eps')  (fma pipe only) ----
    float t0 = 3.0e38f, t1 = 3.0e38f, t2m = 3.0e38f, t3 = 3.0e38f;
    #pragma unroll 8
    for (int jq = 0; jq < DD / 4; jq++) {
        ulonglong2 xq = xs2[jq];
        ull d01 = fma2(aq2, xq.x, c2);
        ull d23 = fma2(aq2, xq.y, c2);
        float da, db, dc, dd;
        upk2(d01, da, db);
        upk2(d23, dc, dd);
        t0  = fminf(t0,  fabsf(da));
        t1  = fminf(t1,  fabsf(db));
        t2m = fminf(t2m, fabsf(dc));
        t3  = fminf(t3,  fabsf(dd));
    }
    float tmin = fmaxf(fminf(fminf(t0, t1), fminf(t2m, t3)), EPS_S);
    float mL2E;   // = L2E * max_j s_j  (rcp monotone decreasing)
    asm("rcp.approx.f32 %0, %1;" : "=f"(mL2E) : "f"(tmin));
    const float negm = -mL2E;

    // Skip threshold: elements with rcp(t) < mL2E - 60 contribute < 2^-60.
    // t > rcp(mL2E - 60)  <=>  skip.  Guard small mL2E -> process everything.
    float thresh;
    if (mL2E > 61.0f) {
        float dn = mL2E - 60.0f;
        asm("rcp.approx.f32 %0, %1;" : "=f"(thresh) : "f"(dn));
    } else {
        thresh = 3.0e38f;
    }

    // ---- Pass 2: per-4-elem warp-vote; heavy path (MUFU) only where hot ----
    ull w2 = 0ULL, w2b = 0ULL, wx2 = 0ULL, wx2b = 0ULL;
    #pragma unroll 4
    for (int jq = 0; jq < DD / 4; jq++) {
        ulonglong2 xq = xs2[jq];
        ull x01 = xq.x, x23 = xq.y;

        ull d01 = fma2(aq2, x01, c2);
        ull d23 = fma2(aq2, x23, c2);
        float da, db, dc, dd;
        upk2(d01, da, db);
        upk2(d23, dc, dd);

        float ta = fmaxf(fabsf(da), EPS_S);
        float tb = fmaxf(fabsf(db), EPS_S);
        float tc = fmaxf(fabsf(dc), EPS_S);
        float td = fmaxf(fabsf(dd), EPS_S);

        float tmn = fminf(fminf(ta, tb), fminf(tc, td));
        if (__any_sync(0xffffffffu, tmn < thresh)) {
            float ra, rb, rc, rd;
            asm("rcp.approx.f32 %0, %1;" : "=f"(ra) : "f"(ta));
            asm("rcp.approx.f32 %0, %1;" : "=f"(rb) : "f"(tb));
            asm("rcp.approx.f32 %0, %1;" : "=f"(rc) : "f"(tc));
            asm("rcp.approx.f32 %0, %1;" : "=f"(rd) : "f"(td));

            float aa = ra + negm;
            float ab = rb + negm;
            float ac = rc + negm;
            float ad = rd + negm;

            float ea, eb, ec, ed;
            asm("ex2.approx.f32 %0, %1;" : "=f"(ea) : "f"(aa));
            asm("ex2.approx.f32 %0, %1;" : "=f"(eb) : "f"(ab));
            asm("ex2.approx.f32 %0, %1;" : "=f"(ec) : "f"(ac));
            asm("ex2.approx.f32 %0, %1;" : "=f"(ed) : "f"(ad));

            ull e01 = pk2(ea, eb);
            ull e23 = pk2(ec, ed);
            w2   = add2(w2,  e01);
            w2b  = add2(w2b, e23);
            wx2  = fma2(e01, x01, wx2);
            wx2b = fma2(e23, x23, wx2b);
        }
    }
    float wl, wh, wbl, wbh, wxl, wxh, wxbl, wxbh;
    upk2(w2, wl, wh);
    upk2(w2b, wbl, wbh);
    upk2(wx2, wxl, wxh);
    upk2(wx2b, wxbl, wxbh);
    float wsum = (wl + wh) + (wbl + wbh);
    float wx   = (wxl + wxh) + (wxbl + wxbh);

    float rw;
    asm("rcp.approx.f32 %0, %1;" : "=f"(rw) : "f"(wsum));
    partial[tid] = av * inv_sqrt_d * (wx * rw);
    __syncthreads();

    // ---- Cross-head sum (8 values per output), single coalesced store ----
    if (tid < ITILE) {
        float bconst = 0.0f;
        #pragma unroll
        for (int hh = 0; hh < HH; hh++) bconst += betas[hh * 3 + 2];

        float s = 0.0f;
        #pragma unroll
        for (int hh = 0; hh < HH; hh++) s += partial[hh * ITILE + tid];

        out[b * DD + tile * ITILE + tid] =
            xs[tile * ITILE + tid] + s + bconst * inv_sqrt_d;
    }
}

extern "C" void kernel_launch(void* const* d_in, const int* in_sizes, int n_in,
                              void* d_out, int out_size)
{
    const float* x      = (const float*)d_in[0];
    const float* alphas = (const float*)d_in[1];
    const float* betas  = (const float*)d_in[2];
    float* out = (float*)d_out;

    dim3 grid(NTILES, BB);   // (32, 64) = 2048 CTAs
    dim3 block(NTHR);
    flattn_kernel<<<grid, block>>>(x, alphas, betas, out);
}

// round 13
// speedup vs baseline: 1.4437x; 1.2518x over previous
#include <cuda_runtime.h>
#include <math.h>

#define BB 64
#define DD 512
#define HH 8
#define EPSF 1e-8f
#define NTHR 256          // 8 warps; warp = head, lanes = 32 sorted positions
#define ITILE 32
#define NTILES (DD / ITILE)   // 16
#define WALK_CAP 64

typedef unsigned long long ull;

__device__ float g_sv[BB * DD];   // sorted x values per batch row
__device__ int   g_si[BB * DD];   // original indices (permutation)

__device__ __forceinline__ ull pk2(float lo, float hi) {
    ull r; asm("mov.b64 %0, {%1, %2};" : "=l"(r) : "f"(lo), "f"(hi)); return r;
}
__device__ __forceinline__ void upk2(ull v, float& lo, float& hi) {
    asm("mov.b64 {%0, %1}, %2;" : "=f"(lo), "=f"(hi) : "l"(v));
}
__device__ __forceinline__ ull fma2(ull a, ull b, ull c) {
    ull r; asm("fma.rn.f32x2 %0, %1, %2, %3;" : "=l"(r) : "l"(a), "l"(b), "l"(c)); return r;
}
__device__ __forceinline__ ull add2(ull a, ull b) {
    ull r; asm("add.rn.f32x2 %0, %1, %2;" : "=l"(r) : "l"(a), "l"(b)); return r;
}
__device__ __forceinline__ float frcp(float v) {
    float r; asm("rcp.approx.f32 %0, %1;" : "=f"(r) : "f"(v)); return r;
}
__device__ __forceinline__ float fex2(float v) {
    float r; asm("ex2.approx.f32 %0, %1;" : "=f"(r) : "f"(v)); return r;
}

// ---------- Kernel 1: bitonic sort of each batch row (value, index) ----------
__global__ __launch_bounds__(256)
void sort_kernel(const float* __restrict__ x)
{
    __shared__ float vals[DD];
    __shared__ int   idxs[DD];
    const int b   = blockIdx.x;
    const int tid = threadIdx.x;

    vals[tid]       = x[b * DD + tid];
    vals[tid + 256] = x[b * DD + tid + 256];
    idxs[tid]       = tid;
    idxs[tid + 256] = tid + 256;
    __syncthreads();

    for (int k = 2; k <= DD; k <<= 1) {
        for (int j = k >> 1; j > 0; j >>= 1) {
            #pragma unroll
            for (int base = 0; base < DD; base += 256) {
                int i = base + tid;
                int p = i ^ j;
                if (p > i) {
                    bool up = ((i & k) == 0);
                    float a = vals[i], c = vals[p];
                    if ((a > c) == up) {
                        vals[i] = c; vals[p] = a;
                        int t = idxs[i]; idxs[i] = idxs[p]; idxs[p] = t;
                    }
                }
            }
            __syncthreads();
        }
    }

    g_sv[b * DD + tid]       = vals[tid];
    g_sv[b * DD + tid + 256] = vals[tid + 256];
    g_si[b * DD + tid]       = idxs[tid];
    g_si[b * DD + tid + 256] = idxs[tid + 256];
}

// ---------- Kernel 2: windowed softmax attention over sorted values ----------
__global__ __launch_bounds__(NTHR)
void flattn_kernel(const float* __restrict__ alphas,
                   const float* __restrict__ betas,
                   float* __restrict__ out)
{
    __shared__ __align__(16) float sv[DD];
    __shared__ float partial[NTHR];   // [h][lane]

    const int b    = blockIdx.y;
    const int tile = blockIdx.x;      // 0..15, block of 32 sorted positions
    const int tid  = threadIdx.x;
    const int h    = tid >> 5;        // warp = head
    const int lane = tid & 31;
    const int pos  = tile * ITILE + lane;   // sorted position this row uses

    // Stage sorted values in shared.
    const float4* svg = (const float4*)(g_sv + b * DD);
    float4* svw = (float4*)sv;
    #pragma unroll
    for (int k = tid; k < DD / 4; k += NTHR) svw[k] = svg[k];
    __syncthreads();

    const float aq = alphas[h * 3 + 0];
    const float ak = alphas[h * 3 + 1];
    const float av = alphas[h * 3 + 2];
    const float bq = betas[h * 3 + 0];
    const float bk = betas[h * 3 + 1];

    const float inv_sqrt_d = 0.044194173824159216f;  // 1/sqrt(512)
    const float INV_L2E    = 0.6931471805599453f;    // ln(2)

    // L2E-scaled domain: rcp(max(|d'|, eps')) = L2E * s feeds ex2 directly.
    const float xi  = sv[pos];
    const float c   = bq - fmaf(ak, xi, bk);   // q_j - k_i = aq*x_j + c
    const float aqs = aq * INV_L2E;
    const float cs  = c  * INV_L2E;
    const float EPS_S = EPSF * INV_L2E;

    // Root of d(x) = aqs*x + cs.
    const float root = -cs * frcp(aqs);

    // Binary search: idx = #elements < root (branchless, 9 fixed steps).
    int idx = 0;
    #pragma unroll
    for (int s = 256; s > 0; s >>= 1) {
        if (sv[idx + s - 1] < root) idx += s;
    }

    // tmin from the two neighbors of the root (t monotone away from root).
    float t_dn = (idx > 0)  ? fabsf(fmaf(aqs, sv[idx - 1], cs)) : 3.0e38f;
    float t_up = (idx < DD) ? fabsf(fmaf(aqs, sv[idx],     cs)) : 3.0e38f;
    float tmin = fmaxf(fminf(t_dn, t_up), EPS_S);
    float mL2E = frcp(tmin);          // = L2E * max_j s_j
    const float negm = -mL2E;

    float wsum = 0.0f, wx = 0.0f;
    bool fb = (mL2E <= 41.0f);        // dense row: all weights comparable

    if (!fb) {
        // Window: t <= thresh  <=>  weight >= ~2^-40 (sum >= 1, so safe).
        float th = frcp(mL2E - 40.0f) * 1.00002f;
        int cnt = 0;
        for (int k = idx - 1; k >= 0; k--) {
            float xv = sv[k];
            float t = fabsf(fmaf(aqs, xv, cs));
            if (t > th) break;
            if (++cnt > WALK_CAP) { fb = true; break; }
            float e = fex2(frcp(fmaxf(t, EPS_S)) + negm);
            wsum += e;
            wx = fmaf(e, xv, wx);
        }
        if (!fb) {
            for (int k = idx; k < DD; k++) {
                float xv = sv[k];
                float t = fabsf(fmaf(aqs, xv, cs));
                if (t > th) break;
                if (++cnt > WALK_CAP) { fb = true; break; }
                float e = fex2(frcp(fmaxf(t, EPS_S)) + negm);
                wsum += e;
                wx = fmaf(e, xv, wx);
            }
        }
    }

    if (fb) {
        // Full packed fallback (R7-style), correct for any row.
        const ull aq2 = pk2(aqs, aqs);
        const ull c2  = pk2(cs, cs);
        const ulonglong2* sv2 = (const ulonglong2*)sv;
        ull w2 = 0ULL, w2b = 0ULL, wx2 = 0ULL, wx2b = 0ULL;
        #pragma unroll 4
        for (int jq = 0; jq < DD / 4; jq++) {
            ulonglong2 xq = sv2[jq];
            ull x01 = xq.x, x23 = xq.y;

            ull d01 = fma2(aq2, x01, c2);
            ull d23 = fma2(aq2, x23, c2);
            float da, db, dc, dd;
            upk2(d01, da, db);
            upk2(d23, dc, dd);

            float ta = fmaxf(fabsf(da), EPS_S);
            float tb = fmaxf(fabsf(db), EPS_S);
            float tc = fmaxf(fabsf(dc), EPS_S);
            float td = fmaxf(fabsf(dd), EPS_S);

            float ea = fex2(frcp(ta) + negm);
            float eb = fex2(frcp(tb) + negm);
            float ec = fex2(frcp(tc) + negm);
            float ed = fex2(frcp(td) + negm);

            ull e01 = pk2(ea, eb);
            ull e23 = pk2(ec, ed);
            w2   = add2(w2,  e01);
            w2b  = add2(w2b, e23);
            wx2  = fma2(e01, x01, wx2);
            wx2b = fma2(e23, x23, wx2b);
        }
        float wl, wh2, wbl, wbh, wxl, wxh, wxbl, wxbh;
        upk2(w2, wl, wh2);
        upk2(w2b, wbl, wbh);
        upk2(wx2, wxl, wxh);
        upk2(wx2b, wxbl, wxbh);
        wsum = (wl + wh2) + (wbl + wbh);
        wx   = (wxl + wxh) + (wxbl + wxbh);
    }

    partial[tid] = av * inv_sqrt_d * (wx * frcp(wsum));
    __syncthreads();

    // ---- Cross-head sum; store to ORIGINAL index (permutation scatter) ----
    if (tid < ITILE) {
        float bconst = 0.0f;
        #pragma unroll
        for (int hh = 0; hh < HH; hh++) bconst += betas[hh * 3 + 2];

        float s = 0.0f;
        #pragma unroll
        for (int hh = 0; hh < HH; hh++) s += partial[hh * ITILE + tid];

        int p  = tile * ITILE + tid;
        int oi = g_si[b * DD + p];
        out[b * DD + oi] = sv[p] + s + bconst * inv_sqrt_d;
    }
}

extern "C" void kernel_launch(void* const* d_in, const int* in_sizes, int n_in,
                              void* d_out, int out_size)
{
    const float* x      = (const float*)d_in[0];
    const float* alphas = (const float*)d_in[1];
    const float* betas  = (const float*)d_in[2];
    float* out = (float*)d_out;

    sort_kernel<<<BB, 256>>>(x);
    dim3 grid(NTILES, BB);   // (16, 64) = 1024 CTAs
    flattn_kernel<<<grid, NTHR>>>(alphas, betas, out);
}

// round 15
// speedup vs baseline: 1.9503x; 1.3510x over previous
#include <cuda_runtime.h>
#include <math.h>

#define BB 64
#define DD 512
#define HH 8
#define EPSF 1e-8f
#define NTHR 256          // 8 warps; warp = head, lanes = 32 sorted positions
#define ITILE 32
#define NTILES (DD / ITILE)   // 16
#define CAPW 128

typedef unsigned long long ull;

__device__ float g_sv[BB * DD];   // sorted x values per batch row
__device__ int   g_si[BB * DD];   // original indices (permutation)

__device__ __forceinline__ ull pk2(float lo, float hi) {
    ull r; asm("mov.b64 %0, {%1, %2};" : "=l"(r) : "f"(lo), "f"(hi)); return r;
}
__device__ __forceinline__ void upk2(ull v, float& lo, float& hi) {
    asm("mov.b64 {%0, %1}, %2;" : "=f"(lo), "=f"(hi) : "l"(v));
}
__device__ __forceinline__ ull fma2(ull a, ull b, ull c) {
    ull r; asm("fma.rn.f32x2 %0, %1, %2, %3;" : "=l"(r) : "l"(a), "l"(b), "l"(c)); return r;
}
__device__ __forceinline__ ull add2(ull a, ull b) {
    ull r; asm("add.rn.f32x2 %0, %1, %2;" : "=l"(r) : "l"(a), "l"(b)); return r;
}
__device__ __forceinline__ float frcp(float v) {
    float r; asm("rcp.approx.f32 %0, %1;" : "=f"(r) : "f"(v)); return r;
}
__device__ __forceinline__ float fex2(float v) {
    float r; asm("ex2.approx.f32 %0, %1;" : "=f"(r) : "f"(v)); return r;
}

// ---------- Kernel 1: bitonic sort of each batch row (value, index) ----------
__global__ __launch_bounds__(256)
void sort_kernel(const float* __restrict__ x)
{
    __shared__ float vals[DD];
    __shared__ int   idxs[DD];
    const int b   = blockIdx.x;
    const int tid = threadIdx.x;

    vals[tid]       = x[b * DD + tid];
    vals[tid + 256] = x[b * DD + tid + 256];
    idxs[tid]       = tid;
    idxs[tid + 256] = tid + 256;
    __syncthreads();

    for (int k = 2; k <= DD; k <<= 1) {
        for (int j = k >> 1; j > 0; j >>= 1) {
            #pragma unroll
            for (int base = 0; base < DD; base += 256) {
                int i = base + tid;
                int p = i ^ j;
                if (p > i) {
                    bool up = ((i & k) == 0);
                    float a = vals[i], c = vals[p];
                    if ((a > c) == up) {
                        vals[i] = c; vals[p] = a;
                        int t = idxs[i]; idxs[i] = idxs[p]; idxs[p] = t;
                    }
                }
            }
            __syncthreads();
        }
    }

    g_sv[b * DD + tid]       = vals[tid];
    g_sv[b * DD + tid + 256] = vals[tid + 256];
    g_si[b * DD + tid]       = idxs[tid];
    g_si[b * DD + tid + 256] = idxs[tid + 256];
}

// ---------- Kernel 2: windowed softmax attention over sorted values ----------
__global__ __launch_bounds__(NTHR)
void flattn_kernel(const float* __restrict__ alphas,
                   const float* __restrict__ betas,
                   float* __restrict__ out)
{
    __shared__ __align__(16) float sv[DD];
    __shared__ float partial[NTHR];   // [h][lane]

    const int b    = blockIdx.y;
    const int tile = blockIdx.x;      // 0..15, block of 32 sorted positions
    const int tid  = threadIdx.x;
    const int h    = tid >> 5;        // warp = head
    const int lane = tid & 31;
    const int pos  = tile * ITILE + lane;   // sorted position this row uses

    // Stage sorted values in shared.
    const float4* svg = (const float4*)(g_sv + b * DD);
    float4* svw = (float4*)sv;
    #pragma unroll
    for (int k = tid; k < DD / 4; k += NTHR) svw[k] = svg[k];
    __syncthreads();

    const float aq = alphas[h * 3 + 0];
    const float ak = alphas[h * 3 + 1];
    const float av = alphas[h * 3 + 2];
    const float bq = betas[h * 3 + 0];
    const float bk = betas[h * 3 + 1];

    const float inv_sqrt_d = 0.044194173824159216f;  // 1/sqrt(512)
    const float INV_L2E    = 0.6931471805599453f;    // ln(2)

    // L2E-scaled domain: rcp(max(|d'|, eps')) = L2E * s feeds ex2 directly.
    const float xi  = sv[pos];
    const float c   = bq - fmaf(ak, xi, bk);   // q_j - k_i = aq*x_j + c
    const float aqs = aq * INV_L2E;
    const float cs  = c  * INV_L2E;
    const float EPS_S = EPSF * INV_L2E;

    // Root of d(x) = aqs*x + cs.
    const float root = -cs * frcp(aqs);

    // Search 1: idx = #elements < root. NOTE: the 9-step loop saturates at 511;
    // the post-loop fixup extends the range to [0, 512].
    int idx = 0;
    #pragma unroll
    for (int s = 256; s > 0; s >>= 1) {
        if (sv[idx + s - 1] < root) idx += s;
    }
    if (sv[idx] < root) idx++;   // idx==511 saturation fixup (sv[511] read safe)

    // tmin over neighbors (hardens against approx-root off-by-one).
    float tmin = 3.0e38f;
    #pragma unroll
    for (int o = -2; o <= 2; o++) {
        int k = idx + o;
        if (k >= 0 && k < DD)
            tmin = fminf(tmin, fabsf(fmaf(aqs, sv[k], cs)));
    }
    tmin = fmaxf(tmin, EPS_S);
    float mL2E = frcp(tmin);          // = L2E * max_j s_j
    const float negm = -mL2E;

    // Window: weight >= ~2^-40  <=>  t <= th  <=>  x in [root-hw, root+hw].
    float th = (mL2E > 41.0f) ? frcp(mL2E - 40.0f) * 1.00002f : 3.0e38f;
    float hw = th * frcp(fabsf(aqs));
    hw = fmaf(fabsf(root), 1e-6f, hw * 1.0001f + 1e-6f);   // rounding margins
    const float xlo = root - hw;
    const float xhi = root + hw;

    // Searches 2+3 interleaved. Same saturation fixup on both:
    // lo = #elements < xlo, hi = #elements <= xhi, each in [0, 512].
    int lo = 0, hi = 0;
    #pragma unroll
    for (int s = 256; s > 0; s >>= 1) {
        if (sv[lo + s - 1] <  xlo) lo += s;
        if (sv[hi + s - 1] <= xhi) hi += s;
    }
    if (sv[lo] <  xlo) lo++;   // saturation fixup -> lo can reach 512
    if (sv[hi] <= xhi) hi++;   // saturation fixup -> hi can reach 512 (incl. sv[511])

    const int nw = hi - lo;
    const bool fb = (nw > CAPW) || (nw < 1);

    float wsum = 0.0f, wx = 0.0f;
    if (!fb) {
        // Counted, break-free window loop (ILP-friendly).
        for (int k = lo; k < hi; k++) {
            float xv = sv[k];
            float t  = fmaxf(fabsf(fmaf(aqs, xv, cs)), EPS_S);
            float e  = fex2(frcp(t) + negm);
            wsum += e;
            wx = fmaf(e, xv, wx);
        }
    } else {
        // Full packed fallback, correct for any row.
        const ull aq2 = pk2(aqs, aqs);
        const ull c2  = pk2(cs, cs);
        const ulonglong2* sv2 = (const ulonglong2*)sv;
        ull w2 = 0ULL, w2b = 0ULL, wx2 = 0ULL, wx2b = 0ULL;
        #pragma unroll 4
        for (int jq = 0; jq < DD / 4; jq++) {
            ulonglong2 xq = sv2[jq];
            ull x01 = xq.x, x23 = xq.y;

            ull d01 = fma2(aq2, x01, c2);
            ull d23 = fma2(aq2, x23, c2);
            float da, db, dc, dd;
            upk2(d01, da, db);
            upk2(d23, dc, dd);

            float ta = fmaxf(fabsf(da), EPS_S);
            float tb = fmaxf(fabsf(db), EPS_S);
            float tc = fmaxf(fabsf(dc), EPS_S);
            float td = fmaxf(fabsf(dd), EPS_S);

            float ea = fex2(frcp(ta) + negm);
            float eb = fex2(frcp(tb) + negm);
            float ec = fex2(frcp(tc) + negm);
            float ed = fex2(frcp(td) + negm);

            ull e01 = pk2(ea, eb);
            ull e23 = pk2(ec, ed);
            w2   = add2(w2,  e01);
            w2b  = add2(w2b, e23);
            wx2  = fma2(e01, x01, wx2);
            wx2b = fma2(e23, x23, wx2b);
        }
        float wl, wh2, wbl, wbh, wxl, wxh, wxbl, wxbh;
        upk2(w2, wl, wh2);
        upk2(w2b, wbl, wbh);
        upk2(wx2, wxl, wxh);
        upk2(wx2b, wxbl, wxbh);
        wsum = (wl + wh2) + (wbl + wbh);
        wx   = (wxl + wxh) + (wxbl + wxbh);
    }

    partial[tid] = av * inv_sqrt_d * (wx * frcp(wsum));
    __syncthreads();

    // ---- Cross-head sum; store to ORIGINAL index (permutation scatter) ----
    if (tid < ITILE) {
        float bconst = 0.0f;
        #pragma unroll
        for (int hh = 0; hh < HH; hh++) bconst += betas[hh * 3 + 2];

        float s = 0.0f;
        #pragma unroll
        for (int hh = 0; hh < HH; hh++) s += partial[hh * ITILE + tid];

        int p  = tile * ITILE + tid;
        int oi = g_si[b * DD + p];
        out[b * DD + oi] = sv[p] + s + bconst * inv_sqrt_d;
    }
}

extern "C" void kernel_launch(void* const* d_in, const int* in_sizes, int n_in,
                              void* d_out, int out_size)
{
    const float* x      = (const float*)d_in[0];
    const float* alphas = (const float*)d_in[1];
    const float* betas  = (const float*)d_in[2];
    float* out = (float*)d_out;

    sort_kernel<<<BB, 256>>>(x);
    dim3 grid(NTILES, BB);   // (16, 64) = 1024 CTAs
    flattn_kernel<<<grid, NTHR>>>(alphas, betas, out);
}

// round 16
// speedup vs baseline: 2.1579x; 1.1064x over previous
#include <cuda_runtime.h>
#include <math.h>

#define BB 64
#define DD 512
#define HH 8
#define EPSF 1e-8f
#define NTHR 256          // 8 warps; warp = head, lanes = 32 sorted positions
#define ITILE 32
#define NTILES (DD / ITILE)   // 16
#define CAPW 32           // sparse window cap
#define DENSE_T 12        // >= this many dense lanes -> lockstep packed path

typedef unsigned long long ull;

__device__ float g_sv[BB * DD];   // sorted x values per batch row
__device__ int   g_si[BB * DD];   // original indices (permutation)

__device__ __forceinline__ ull pk2(float lo, float hi) {
    ull r; asm("mov.b64 %0, {%1, %2};" : "=l"(r) : "f"(lo), "f"(hi)); return r;
}
__device__ __forceinline__ void upk2(ull v, float& lo, float& hi) {
    asm("mov.b64 {%0, %1}, %2;" : "=f"(lo), "=f"(hi) : "l"(v));
}
__device__ __forceinline__ ull fma2(ull a, ull b, ull c) {
    ull r; asm("fma.rn.f32x2 %0, %1, %2, %3;" : "=l"(r) : "l"(a), "l"(b), "l"(c)); return r;
}
__device__ __forceinline__ ull add2(ull a, ull b) {
    ull r; asm("add.rn.f32x2 %0, %1, %2;" : "=l"(r) : "l"(a), "l"(b)); return r;
}
__device__ __forceinline__ float frcp(float v) {
    float r; asm("rcp.approx.f32 %0, %1;" : "=f"(r) : "f"(v)); return r;
}
__device__ __forceinline__ float fex2(float v) {
    float r; asm("ex2.approx.f32 %0, %1;" : "=f"(r) : "f"(v)); return r;
}
__device__ __forceinline__ int redux_max_u32(int v) {
    int r; asm("redux.sync.max.u32 %0, %1, 0xffffffff;" : "=r"(r) : "r"(v)); return r;
}

// ---------- Kernel 1: bitonic sort of each batch row (value, index) ----------
__global__ __launch_bounds__(256)
void sort_kernel(const float* __restrict__ x)
{
    __shared__ float vals[DD];
    __shared__ int   idxs[DD];
    const int b   = blockIdx.x;
    const int tid = threadIdx.x;

    vals[tid]       = x[b * DD + tid];
    vals[tid + 256] = x[b * DD + tid + 256];
    idxs[tid]       = tid;
    idxs[tid + 256] = tid + 256;
    __syncthreads();

    for (int k = 2; k <= DD; k <<= 1) {
        for (int j = k >> 1; j > 0; j >>= 1) {
            #pragma unroll
            for (int base = 0; base < DD; base += 256) {
                int i = base + tid;
                int p = i ^ j;
                if (p > i) {
                    bool up = ((i & k) == 0);
                    float a = vals[i], c = vals[p];
                    if ((a > c) == up) {
                        vals[i] = c; vals[p] = a;
                        int t = idxs[i]; idxs[i] = idxs[p]; idxs[p] = t;
                    }
                }
            }
            __syncthreads();
        }
    }

    g_sv[b * DD + tid]       = vals[tid];
    g_sv[b * DD + tid + 256] = vals[tid + 256];
    g_si[b * DD + tid]       = idxs[tid];
    g_si[b * DD + tid + 256] = idxs[tid + 256];
}

// ---------- Kernel 2: windowed softmax attention over sorted values ----------
__global__ __launch_bounds__(NTHR)
void flattn_kernel(const float* __restrict__ alphas,
                   const float* __restrict__ betas,
                   float* __restrict__ out)
{
    __shared__ __align__(16) float sv[DD];
    __shared__ float partial[NTHR];   // [h][lane]

    const int b    = blockIdx.y;
    const int tile = blockIdx.x;      // 0..15, block of 32 sorted positions
    const int tid  = threadIdx.x;
    const int h    = tid >> 5;        // warp = head (aqs warp-uniform!)
    const int lane = tid & 31;
    const int pos  = tile * ITILE + lane;

    const float4* svg = (const float4*)(g_sv + b * DD);
    float4* svw = (float4*)sv;
    #pragma unroll
    for (int k = tid; k < DD / 4; k += NTHR) svw[k] = svg[k];
    __syncthreads();

    const float aq = alphas[h * 3 + 0];
    const float ak = alphas[h * 3 + 1];
    const float av = alphas[h * 3 + 2];
    const float bq = betas[h * 3 + 0];
    const float bk = betas[h * 3 + 1];

    const float inv_sqrt_d = 0.044194173824159216f;  // 1/sqrt(512)
    const float INV_L2E    = 0.6931471805599453f;    // ln(2)

    const float xi  = sv[pos];
    const float c   = bq - fmaf(ak, xi, bk);   // q_j - k_i = aq*x_j + c
    const float aqs = aq * INV_L2E;            // warp-uniform
    const float cs  = c  * INV_L2E;            // per-lane
    const float EPS_S = EPSF * INV_L2E;

    const float root = -cs * frcp(aqs);

    // Search 1: idx = #elements < root (9 steps + saturation fixup).
    int idx = 0;
    #pragma unroll
    for (int s = 256; s > 0; s >>= 1) {
        if (sv[idx + s - 1] < root) idx += s;
    }
    if (sv[idx] < root) idx++;

    float tmin = 3.0e38f;
    #pragma unroll
    for (int o = -2; o <= 2; o++) {
        int k = idx + o;
        if (k >= 0 && k < DD)
            tmin = fminf(tmin, fabsf(fmaf(aqs, sv[k], cs)));
    }
    tmin = fmaxf(tmin, EPS_S);
    float mL2E = frcp(tmin);
    const float negm = -mL2E;

    // Window: weight >= ~2^-40  <=>  x in [root-hw, root+hw].
    float th = (mL2E > 41.0f) ? frcp(mL2E - 40.0f) * 1.00002f : 3.0e38f;
    float hw = th * frcp(fabsf(aqs));
    hw = fmaf(fabsf(root), 1e-6f, hw * 1.0001f + 1e-6f);
    const float xlo = root - hw;
    const float xhi = root + hw;

    // Searches 2+3 interleaved, with saturation fixups ([0, 512] range).
    int lo = 0, hi = 0;
    #pragma unroll
    for (int s = 256; s > 0; s >>= 1) {
        if (sv[lo + s - 1] <  xlo) lo += s;
        if (sv[hi + s - 1] <= xhi) hi += s;
    }
    if (sv[lo] <  xlo) lo++;
    if (sv[hi] <= xhi) hi++;

    int nw = hi - lo;
    bool dense = (nw > CAPW) || (nw < 1);
    if (nw < 1) { lo = 0; hi = DD; }          // safety: full range in coop path

    const unsigned FULL = 0xffffffffu;
    unsigned dmask = __ballot_sync(FULL, dense);
    int nd = __popc(dmask);

    float wsum = 0.0f, wx = 0.0f;

    // ---- Tier 1: sparse lanes, lockstep counted loop to warp-max nw ----
    int nws = dense ? 0 : nw;
    int nwmax = redux_max_u32(nws);
    for (int t = 0; t < nwmax; t++) {
        int k = lo + t;
        if (!dense && k < hi) {
            float xv = sv[k];
            float tt = fmaxf(fabsf(fmaf(aqs, xv, cs)), EPS_S);
            float e  = fex2(frcp(tt) + negm);
            wsum += e;
            wx = fmaf(e, xv, wx);
        }
    }

    if (nd >= DENSE_T) {
        // ---- Tier 3: many dense lanes -> packed full loop (per-lane) ----
        if (dense) {
            const ull aq2 = pk2(aqs, aqs);
            const ull c2  = pk2(cs, cs);
            const ulonglong2* sv2 = (const ulonglong2*)sv;
            ull w2 = 0ULL, w2b = 0ULL, wx2 = 0ULL, wx2b = 0ULL;
            #pragma unroll 4
            for (int jq = 0; jq < DD / 4; jq++) {
                ulonglong2 xq = sv2[jq];
                ull x01 = xq.x, x23 = xq.y;

                ull d01 = fma2(aq2, x01, c2);
                ull d23 = fma2(aq2, x23, c2);
                float da, db, dc, dd;
                upk2(d01, da, db);
                upk2(d23, dc, dd);

                float ta = fmaxf(fabsf(da), EPS_S);
                float tb = fmaxf(fabsf(db), EPS_S);
                float tc = fmaxf(fabsf(dc), EPS_S);
                float td = fmaxf(fabsf(dd), EPS_S);

                float ea = fex2(frcp(ta) + negm);
                float eb = fex2(frcp(tb) + negm);
                float ec = fex2(frcp(tc) + negm);
                float ed = fex2(frcp(td) + negm);

                ull e01 = pk2(ea, eb);
                ull e23 = pk2(ec, ed);
                w2   = add2(w2,  e01);
                w2b  = add2(w2b, e23);
                wx2  = fma2(e01, x01, wx2);
                wx2b = fma2(e23, x23, wx2b);
            }
            float wl, wh2, wbl, wbh, wxl, wxh, wxbl, wxbh;
            upk2(w2, wl, wh2);
            upk2(w2b, wbl, wbh);
            upk2(wx2, wxl, wxh);
            upk2(wx2b, wxbl, wxbh);
            wsum = (wl + wh2) + (wbl + wbh);
            wx   = (wxl + wxh) + (wxbl + wxbh);
        }
    } else {
        // ---- Tier 2: few dense rows -> warp-cooperative, one row at a time ----
        while (dmask) {
            int r = __ffs(dmask) - 1;
            dmask &= dmask - 1;
            int   lor   = __shfl_sync(FULL, lo,   r);
            int   hir   = __shfl_sync(FULL, hi,   r);
            float csr   = __shfl_sync(FULL, cs,   r);
            float negmr = __shfl_sync(FULL, negm, r);

            float ws = 0.0f, wxr = 0.0f;
            for (int k = lor + lane; k < hir; k += 32) {
                float xv = sv[k];
                float tt = fmaxf(fabsf(fmaf(aqs, xv, csr)), EPS_S);
                float e  = fex2(frcp(tt) + negmr);
                ws += e;
                wxr = fmaf(e, xv, wxr);
            }
            #pragma unroll
            for (int o = 16; o > 0; o >>= 1) {
                ws  += __shfl_xor_sync(FULL, ws,  o);
                wxr += __shfl_xor_sync(FULL, wxr, o);
            }
            if (lane == r) { wsum = ws; wx = wxr; }
        }
    }

    partial[tid] = av * inv_sqrt_d * (wx * frcp(wsum));
    __syncthreads();

    // ---- Cross-head sum; store to ORIGINAL index (permutation scatter) ----
    if (tid < ITILE) {
        float bconst = 0.0f;
        #pragma unroll
        for (int hh = 0; hh < HH; hh++) bconst += betas[hh * 3 + 2];

        float s = 0.0f;
        #pragma unroll
        for (int hh = 0; hh < HH; hh++) s += partial[hh * ITILE + tid];

        int p  = tile * ITILE + tid;
        int oi = g_si[b * DD + p];
        out[b * DD + oi] = sv[p] + s + bconst * inv_sqrt_d;
    }
}

extern "C" void kernel_launch(void* const* d_in, const int* in_sizes, int n_in,
                              void* d_out, int out_size)
{
    const float* x      = (const float*)d_in[0];
    const float* alphas = (const float*)d_in[1];
    const float* betas  = (const float*)d_in[2];
    float* out = (float*)d_out;

    sort_kernel<<<BB, 256>>>(x);
    dim3 grid(NTILES, BB);   // (16, 64) = 1024 CTAs
    flattn_kernel<<<grid, NTHR>>>(alphas, betas, out);
}